// round 16
// baseline (speedup 1.0000x reference)
#include <cuda_runtime.h>

#define NN    50000
#define DIN   128
#define DOUT  64
#define EE    800000
#define GTILE 64          // nodes per GEMM block
#define SHPAD 132         // padded sH row stride (breaks bank conflicts)
#define NSB   196         // scan blocks (196*256 >= NN)

#define FLAG_AGG 0x40000000u
#define FLAG_INC 0x80000000u
#define VAL_MASK 0x3FFFFFFFu

// ---------------------------------------------------------------------------
// Device scratch
// ---------------------------------------------------------------------------
__device__ float  g_X[NN * DOUT];        // projected features
__device__ int    g_cnt[NN];             // degree counters (all-zero invariant)
__device__ int    g_cur[NN];             // scatter cursors
__device__ int    g_rowptr[NN + 1];      // CSR row offsets
__device__ volatile unsigned g_lk[NSB];  // lookback state (flag|value packed)
__device__ float2 g_edge[EE];            // CSR (col as int bits, val)

// ---------------------------------------------------------------------------
// hist: 4 edges per thread; block 0 also clears the lookback flags
// (safe: scan kernel launches only after hist completes).
// ---------------------------------------------------------------------------
__global__ void hist_kernel(const int* __restrict__ rows) {
    int t = blockIdx.x * blockDim.x + threadIdx.x;
    if (blockIdx.x == 0 && threadIdx.x < NSB)
        g_lk[threadIdx.x] = 0u;
    if (t < EE / 4) {
        int4 r = reinterpret_cast<const int4*>(rows)[t];
        atomicAdd(&g_cnt[r.x], 1);
        atomicAdd(&g_cnt[r.y], 1);
        atomicAdd(&g_cnt[r.z], 1);
        atomicAdd(&g_cnt[r.w], 1);
    }
}

// ---------------------------------------------------------------------------
// Single-pass decoupled-lookback scan over the 50K degrees.
// Reads AND zeroes g_cnt (restores invariant for the next graph replay).
// Produces g_rowptr and seeds g_cur.
// ---------------------------------------------------------------------------
__global__ __launch_bounds__(256) void scan_kernel() {
    __shared__ int  wsum[8];
    __shared__ int  sBase;

    const int tid  = threadIdx.x;
    const int b    = blockIdx.x;
    const int i    = b * 256 + tid;
    const int lane = tid & 31, warp = tid >> 5;

    // load degree, zero it
    int val = 0;
    if (i < NN) {
        val = g_cnt[i];
        g_cnt[i] = 0;
    }

    // block-wide inclusive scan
    int v = val;
    #pragma unroll
    for (int o = 1; o < 32; o <<= 1) {
        int n = __shfl_up_sync(0xffffffffu, v, o);
        if (lane >= o) v += n;
    }
    if (lane == 31) wsum[warp] = v;
    __syncthreads();
    if (warp == 0 && lane < 8) {
        int s = wsum[lane];
        #pragma unroll
        for (int o = 1; o < 8; o <<= 1) {
            int n = __shfl_up_sync(0xffu, s, o);
            if (lane >= o) s += n;
        }
        wsum[lane] = s;
    }
    __syncthreads();
    int incl  = v + ((warp > 0) ? wsum[warp - 1] : 0);
    int total = wsum[7];

    // decoupled lookback (single packed word per block; no extra fences)
    if (tid == 0) {
        if (b == 0) {
            atomicExch((unsigned*)&g_lk[0], FLAG_INC | (unsigned)total);
            sBase = 0;
        } else {
            atomicExch((unsigned*)&g_lk[b], FLAG_AGG | (unsigned)total);
            int running = 0;
            int p = b - 1;
            while (true) {
                unsigned w = g_lk[p];          // volatile read
                if (w & FLAG_INC) { running += (int)(w & VAL_MASK); break; }
                if (w & FLAG_AGG) { running += (int)(w & VAL_MASK); --p; }
                // else: not yet published — spin
            }
            atomicExch((unsigned*)&g_lk[b],
                       FLAG_INC | (unsigned)(running + total));
            sBase = running;
        }
    }
    __syncthreads();

    if (i < NN) {
        int r = sBase + incl - val;   // exclusive prefix
        g_rowptr[i] = r;
        g_cur[i]    = r;
    }
    if (b == 0 && tid == 0) g_rowptr[NN] = EE;
}

// ---------------------------------------------------------------------------
// scatter: 4 edges per thread, packed 8B records
// ---------------------------------------------------------------------------
__global__ void scatter_kernel(const int* __restrict__ rows,
                               const int* __restrict__ cols,
                               const float* __restrict__ vals) {
    int t = blockIdx.x * blockDim.x + threadIdx.x;
    if (t < EE / 4) {
        int4   r = reinterpret_cast<const int4*>(rows)[t];
        int4   c = reinterpret_cast<const int4*>(cols)[t];
        float4 v = reinterpret_cast<const float4*>(vals)[t];
        int p0 = atomicAdd(&g_cur[r.x], 1);
        int p1 = atomicAdd(&g_cur[r.y], 1);
        int p2 = atomicAdd(&g_cur[r.z], 1);
        int p3 = atomicAdd(&g_cur[r.w], 1);
        g_edge[p0] = make_float2(__int_as_float(c.x), v.x);
        g_edge[p1] = make_float2(__int_as_float(c.y), v.y);
        g_edge[p2] = make_float2(__int_as_float(c.z), v.z);
        g_edge[p3] = make_float2(__int_as_float(c.w), v.w);
    }
}

// ---------------------------------------------------------------------------
// Fused L2-normalize + BN(eval) + Linear(128->64)+bias -> g_X  (proven)
// ---------------------------------------------------------------------------
__global__ __launch_bounds__(128) void fused_gemm_kernel(
    const float* __restrict__ H,
    const float* __restrict__ gamma,
    const float* __restrict__ beta,
    const float* __restrict__ mean,
    const float* __restrict__ var,
    const float* __restrict__ W,
    const float* __restrict__ bias)
{
    __shared__ float sW[DIN * DOUT];
    __shared__ float sH[GTILE * SHPAD];
    __shared__ float sA[DIN];
    __shared__ float sC[DIN];
    __shared__ float sInv[GTILE];

    const int tid    = threadIdx.x;
    const int node0  = blockIdx.x * GTILE;
    const int nvalid = min(GTILE, NN - node0);

    #pragma unroll
    for (int i = tid; i < DIN * DOUT / 4; i += 128)
        reinterpret_cast<float4*>(sW)[i] =
            reinterpret_cast<const float4*>(W)[i];

    {
        float a = gamma[tid] * rsqrtf(var[tid] + 1e-5f);
        sA[tid] = a;
        sC[tid] = beta[tid] - mean[tid] * a;
    }

    #pragma unroll
    for (int i4 = tid; i4 < GTILE * (DIN / 4); i4 += 128) {
        int r = i4 >> 5;
        int c = (i4 & 31) * 4;
        float4 v = (r < nvalid)
            ? reinterpret_cast<const float4*>(H)[(node0 + r) * (DIN / 4) + (c >> 2)]
            : make_float4(1.f, 0.f, 0.f, 0.f);
        *reinterpret_cast<float4*>(&sH[r * SHPAD + c]) = v;
    }
    __syncthreads();

    {
        int r = tid >> 1, l = tid & 1;
        float ss = 0.f;
        #pragma unroll
        for (int i = 0; i < 16; i++) {
            float4 v = *reinterpret_cast<float4*>(&sH[r * SHPAD + l * 64 + i * 4]);
            ss += v.x * v.x + v.y * v.y + v.z * v.z + v.w * v.w;
        }
        ss += __shfl_xor_sync(0xffffffffu, ss, 1);
        if (l == 0) sInv[r] = 1.0f / fmaxf(sqrtf(ss), 1e-12f);
    }
    __syncthreads();

    #pragma unroll
    for (int i4 = tid; i4 < GTILE * (DIN / 4); i4 += 128) {
        int r = i4 >> 5;
        int c = (i4 & 31) * 4;
        float inv = sInv[r];
        float4 h  = *reinterpret_cast<float4*>(&sH[r * SHPAD + c]);
        float4 a  = *reinterpret_cast<float4*>(&sA[c]);
        float4 cc = *reinterpret_cast<float4*>(&sC[c]);
        h.x = fmaf(h.x * inv, a.x, cc.x);
        h.y = fmaf(h.y * inv, a.y, cc.y);
        h.z = fmaf(h.z * inv, a.z, cc.z);
        h.w = fmaf(h.w * inv, a.w, cc.w);
        *reinterpret_cast<float4*>(&sH[r * SHPAD + c]) = h;
    }
    __syncthreads();

    const int jg = tid & 15;
    const int ng = tid >> 4;
    const int n0 = ng * 8;
    const int j0 = jg * 4;

    float4 acc[8];
    #pragma unroll
    for (int i = 0; i < 8; i++) acc[i] = make_float4(0.f, 0.f, 0.f, 0.f);

    #pragma unroll 4
    for (int k = 0; k < DIN; k++) {
        float4 w = *reinterpret_cast<float4*>(&sW[k * DOUT + j0]);
        #pragma unroll
        for (int i = 0; i < 8; i++) {
            float h = sH[(n0 + i) * SHPAD + k];
            acc[i].x = fmaf(h, w.x, acc[i].x);
            acc[i].y = fmaf(h, w.y, acc[i].y);
            acc[i].z = fmaf(h, w.z, acc[i].z);
            acc[i].w = fmaf(h, w.w, acc[i].w);
        }
    }

    float4 bb = *reinterpret_cast<const float4*>(&bias[j0]);
    #pragma unroll
    for (int i = 0; i < 8; i++) {
        if (n0 + i < nvalid) {
            float4 a = acc[i];
            a.x += bb.x; a.y += bb.y; a.z += bb.z; a.w += bb.w;
            *reinterpret_cast<float4*>(&g_X[(node0 + n0 + i) * DOUT + j0]) = a;
        }
    }
}

// ---------------------------------------------------------------------------
// SpMM + LeakyReLU (R15-proven): 16 lanes/row, shfl-batched edge records
// ---------------------------------------------------------------------------
__global__ __launch_bounds__(256) void spmm_leaky_kernel(float* __restrict__ out)
{
    int gid  = blockIdx.x * 256 + threadIdx.x;
    int row  = gid >> 4;
    if (row >= NN) return;
    int sub  = gid & 15;
    int c0   = sub * 4;

    int s = g_rowptr[row];
    int e = g_rowptr[row + 1];

    float4 a = make_float4(0.f, 0.f, 0.f, 0.f);

    for (int base = s; base < e; base += 16) {
        int   ep = base + sub;
        float2 ev = (ep < e) ? g_edge[ep] : make_float2(__int_as_float(0), 0.f);
        int ci = __float_as_int(ev.x);
        int cnt = min(16, e - base);

        #pragma unroll 4
        for (int j = 0; j < cnt; j++) {
            int   col = __shfl_sync(0xffffffffu, ci,   j, 16);
            float v   = __shfl_sync(0xffffffffu, ev.y, j, 16);
            float4 x  = *reinterpret_cast<const float4*>(&g_X[col * DOUT + c0]);
            a.x = fmaf(v, x.x, a.x);
            a.y = fmaf(v, x.y, a.y);
            a.z = fmaf(v, x.z, a.z);
            a.w = fmaf(v, x.w, a.w);
        }
    }

    a.x = a.x >= 0.f ? a.x : 0.01f * a.x;
    a.y = a.y >= 0.f ? a.y : 0.01f * a.y;
    a.z = a.z >= 0.f ? a.z : 0.01f * a.z;
    a.w = a.w >= 0.f ? a.w : 0.01f * a.w;

    *reinterpret_cast<float4*>(&out[row * DOUT + c0]) = a;
}

// ---------------------------------------------------------------------------
// Launch: CSR chain (3 kernels) on s0 ∥ GEMM on s1; SpMM joins.
// ---------------------------------------------------------------------------
extern "C" void kernel_launch(void* const* d_in, const int* in_sizes, int n_in,
                              void* d_out, int out_size) {
    const float* H     = (const float*)d_in[0];
    const int*   rows  = (const int*)  d_in[1];
    const int*   cols  = (const int*)  d_in[2];
    const float* vals  = (const float*)d_in[3];
    const float* gamma = (const float*)d_in[4];
    const float* beta  = (const float*)d_in[5];
    const float* rmean = (const float*)d_in[6];
    const float* rvar  = (const float*)d_in[7];
    const float* W     = (const float*)d_in[8];
    const float* b     = (const float*)d_in[9];
    float* out = (float*)d_out;

    cudaStream_t s0 = 0;
    cudaStream_t s1;
    cudaEvent_t  evFork, evJoin;
    cudaStreamCreateWithFlags(&s1, cudaStreamNonBlocking);
    cudaEventCreateWithFlags(&evFork, cudaEventDisableTiming);
    cudaEventCreateWithFlags(&evJoin, cudaEventDisableTiming);

    // Fork: GEMM on s1
    cudaEventRecord(evFork, s0);
    cudaStreamWaitEvent(s1, evFork, 0);
    fused_gemm_kernel<<<(NN + GTILE - 1) / GTILE, 128, 0, s1>>>(
        H, gamma, beta, rmean, rvar, W, b);
    cudaEventRecord(evJoin, s1);

    // CSR build chain on s0 (concurrent with GEMM)
    hist_kernel<<<(EE / 4 + 255) / 256, 256, 0, s0>>>(rows);
    scan_kernel<<<NSB, 256, 0, s0>>>();
    scatter_kernel<<<(EE / 4 + 255) / 256, 256, 0, s0>>>(rows, cols, vals);

    // Join: SpMM needs both g_X (s1) and CSR arrays (s0)
    cudaStreamWaitEvent(s0, evJoin, 0);
    spmm_leaky_kernel<<<(NN * 16 + 255) / 256, 256, 0, s0>>>(out);

    cudaEventDestroy(evFork);
    cudaEventDestroy(evJoin);
    cudaStreamDestroy(s1);
}

// round 17
// speedup vs baseline: 1.0794x; 1.0794x over previous
#include <cuda_runtime.h>

#define NN    50000
#define DIN   128
#define DOUT  64
#define EE    800000
#define GTILE 64          // nodes per GEMM block
#define SHPAD 132         // padded sH row stride (breaks bank conflicts)
#define NSB   196         // scan blocks (196*256 >= NN)

#define FLAG_AGG 0x40000000u
#define FLAG_INC 0x80000000u
#define VAL_MASK 0x3FFFFFFFu
#define FULL     0xffffffffu

// ---------------------------------------------------------------------------
// Device scratch
// ---------------------------------------------------------------------------
__device__ float  g_X[NN * DOUT];        // projected features
__device__ int    g_cnt[NN];             // degree counters (all-zero invariant)
__device__ int    g_cur[NN];             // scatter cursors
__device__ int    g_rowptr[NN + 1];      // CSR row offsets
__device__ volatile unsigned g_lk[NSB];  // lookback state (flag|value packed)
__device__ float2 g_edge[EE];            // CSR (col as int bits, val)

// ---------------------------------------------------------------------------
// hist: 4 edges per thread; block 0 also clears the lookback flags
// (safe: the scan kernel only launches after hist completes).
// ---------------------------------------------------------------------------
__global__ void hist_kernel(const int* __restrict__ rows) {
    if (blockIdx.x == 0 && threadIdx.x < NSB)
        g_lk[threadIdx.x] = 0u;
    int t = blockIdx.x * blockDim.x + threadIdx.x;
    if (t < EE / 4) {
        int4 r = reinterpret_cast<const int4*>(rows)[t];
        atomicAdd(&g_cnt[r.x], 1);
        atomicAdd(&g_cnt[r.y], 1);
        atomicAdd(&g_cnt[r.z], 1);
        atomicAdd(&g_cnt[r.w], 1);
    }
}

// ---------------------------------------------------------------------------
// Single-pass scan with WARP-PARALLEL decoupled lookback.
// Reads AND zeroes g_cnt; produces g_rowptr; seeds g_cur.
// ---------------------------------------------------------------------------
__global__ __launch_bounds__(256) void scan_kernel() {
    __shared__ int wsum[8];
    __shared__ int sBase;

    const int tid  = threadIdx.x;
    const int b    = blockIdx.x;
    const int i    = b * 256 + tid;
    const int lane = tid & 31, warp = tid >> 5;

    // load degree, zero it (restores invariant for the next graph replay)
    int val = 0;
    if (i < NN) {
        val = g_cnt[i];
        g_cnt[i] = 0;
    }

    // block-wide inclusive scan
    int v = val;
    #pragma unroll
    for (int o = 1; o < 32; o <<= 1) {
        int n = __shfl_up_sync(FULL, v, o);
        if (lane >= o) v += n;
    }
    if (lane == 31) wsum[warp] = v;
    __syncthreads();
    if (warp == 0 && lane < 8) {
        int s = wsum[lane];
        #pragma unroll
        for (int o = 1; o < 8; o <<= 1) {
            int n = __shfl_up_sync(0xffu, s, o);
            if (lane >= o) s += n;
        }
        wsum[lane] = s;
    }
    __syncthreads();
    int incl  = v + ((warp > 0) ? wsum[warp - 1] : 0);
    int total = wsum[7];

    // warp-parallel decoupled lookback (warp 0)
    if (warp == 0) {
        if (b == 0) {
            if (lane == 0) {
                atomicExch((unsigned*)&g_lk[0], FLAG_INC | (unsigned)total);
                sBase = 0;
            }
        } else {
            if (lane == 0)
                atomicExch((unsigned*)&g_lk[b], FLAG_AGG | (unsigned)total);
            __syncwarp();

            int running = 0;
            int p = b - 1;                       // window = [p-31, p]
            while (true) {
                int idx = p - 31 + lane;
                // virtual INC(0) below index 0 terminates the walk
                unsigned w = (idx >= 0) ? g_lk[idx] : FLAG_INC;
                bool valid = (w & 0xC0000000u) != 0u;
                if (!__all_sync(FULL, valid)) continue;   // someone unpublished

                unsigned incmask = __ballot_sync(FULL, (w & FLAG_INC) != 0u);
                if (incmask) {
                    int hi = 31 - __clz(incmask);         // highest INC lane
                    int contrib = (lane >= hi) ? (int)(w & VAL_MASK) : 0;
                    #pragma unroll
                    for (int o = 16; o > 0; o >>= 1)
                        contrib += __shfl_xor_sync(FULL, contrib, o);
                    running += contrib;
                    break;
                } else {
                    int contrib = (int)(w & VAL_MASK);
                    #pragma unroll
                    for (int o = 16; o > 0; o >>= 1)
                        contrib += __shfl_xor_sync(FULL, contrib, o);
                    running += contrib;
                    p -= 32;
                }
            }
            if (lane == 0) {
                atomicExch((unsigned*)&g_lk[b],
                           FLAG_INC | (unsigned)(running + total));
                sBase = running;
            }
        }
    }
    __syncthreads();

    if (i < NN) {
        int r = sBase + incl - val;   // exclusive prefix
        g_rowptr[i] = r;
        g_cur[i]    = r;
    }
    if (b == 0 && tid == 0) g_rowptr[NN] = EE;
}

// ---------------------------------------------------------------------------
// scatter: one edge per thread, packed 8B record (R15-proven)
// ---------------------------------------------------------------------------
__global__ void scatter_kernel(const int* __restrict__ rows,
                               const int* __restrict__ cols,
                               const float* __restrict__ vals) {
    int e = blockIdx.x * blockDim.x + threadIdx.x;
    if (e < EE) {
        int pos = atomicAdd(&g_cur[rows[e]], 1);
        g_edge[pos] = make_float2(__int_as_float(cols[e]), vals[e]);
    }
}

// ---------------------------------------------------------------------------
// Fused L2-normalize + BN(eval) + Linear(128->64)+bias -> g_X  (proven)
// ---------------------------------------------------------------------------
__global__ __launch_bounds__(128) void fused_gemm_kernel(
    const float* __restrict__ H,
    const float* __restrict__ gamma,
    const float* __restrict__ beta,
    const float* __restrict__ mean,
    const float* __restrict__ var,
    const float* __restrict__ W,
    const float* __restrict__ bias)
{
    __shared__ float sW[DIN * DOUT];
    __shared__ float sH[GTILE * SHPAD];
    __shared__ float sA[DIN];
    __shared__ float sC[DIN];
    __shared__ float sInv[GTILE];

    const int tid    = threadIdx.x;
    const int node0  = blockIdx.x * GTILE;
    const int nvalid = min(GTILE, NN - node0);

    #pragma unroll
    for (int i = tid; i < DIN * DOUT / 4; i += 128)
        reinterpret_cast<float4*>(sW)[i] =
            reinterpret_cast<const float4*>(W)[i];

    {
        float a = gamma[tid] * rsqrtf(var[tid] + 1e-5f);
        sA[tid] = a;
        sC[tid] = beta[tid] - mean[tid] * a;
    }

    #pragma unroll
    for (int i4 = tid; i4 < GTILE * (DIN / 4); i4 += 128) {
        int r = i4 >> 5;
        int c = (i4 & 31) * 4;
        float4 v = (r < nvalid)
            ? reinterpret_cast<const float4*>(H)[(node0 + r) * (DIN / 4) + (c >> 2)]
            : make_float4(1.f, 0.f, 0.f, 0.f);
        *reinterpret_cast<float4*>(&sH[r * SHPAD + c]) = v;
    }
    __syncthreads();

    {
        int r = tid >> 1, l = tid & 1;
        float ss = 0.f;
        #pragma unroll
        for (int i = 0; i < 16; i++) {
            float4 v = *reinterpret_cast<float4*>(&sH[r * SHPAD + l * 64 + i * 4]);
            ss += v.x * v.x + v.y * v.y + v.z * v.z + v.w * v.w;
        }
        ss += __shfl_xor_sync(FULL, ss, 1);
        if (l == 0) sInv[r] = 1.0f / fmaxf(sqrtf(ss), 1e-12f);
    }
    __syncthreads();

    #pragma unroll
    for (int i4 = tid; i4 < GTILE * (DIN / 4); i4 += 128) {
        int r = i4 >> 5;
        int c = (i4 & 31) * 4;
        float inv = sInv[r];
        float4 h  = *reinterpret_cast<float4*>(&sH[r * SHPAD + c]);
        float4 a  = *reinterpret_cast<float4*>(&sA[c]);
        float4 cc = *reinterpret_cast<float4*>(&sC[c]);
        h.x = fmaf(h.x * inv, a.x, cc.x);
        h.y = fmaf(h.y * inv, a.y, cc.y);
        h.z = fmaf(h.z * inv, a.z, cc.z);
        h.w = fmaf(h.w * inv, a.w, cc.w);
        *reinterpret_cast<float4*>(&sH[r * SHPAD + c]) = h;
    }
    __syncthreads();

    const int jg = tid & 15;
    const int ng = tid >> 4;
    const int n0 = ng * 8;
    const int j0 = jg * 4;

    float4 acc[8];
    #pragma unroll
    for (int i = 0; i < 8; i++) acc[i] = make_float4(0.f, 0.f, 0.f, 0.f);

    #pragma unroll 4
    for (int k = 0; k < DIN; k++) {
        float4 w = *reinterpret_cast<float4*>(&sW[k * DOUT + j0]);
        #pragma unroll
        for (int i = 0; i < 8; i++) {
            float h = sH[(n0 + i) * SHPAD + k];
            acc[i].x = fmaf(h, w.x, acc[i].x);
            acc[i].y = fmaf(h, w.y, acc[i].y);
            acc[i].z = fmaf(h, w.z, acc[i].z);
            acc[i].w = fmaf(h, w.w, acc[i].w);
        }
    }

    float4 bb = *reinterpret_cast<const float4*>(&bias[j0]);
    #pragma unroll
    for (int i = 0; i < 8; i++) {
        if (n0 + i < nvalid) {
            float4 a = acc[i];
            a.x += bb.x; a.y += bb.y; a.z += bb.z; a.w += bb.w;
            *reinterpret_cast<float4*>(&g_X[(node0 + n0 + i) * DOUT + j0]) = a;
        }
    }
}

// ---------------------------------------------------------------------------
// SpMM + LeakyReLU (R15-proven): 16 lanes/row, shfl-batched edge records
// ---------------------------------------------------------------------------
__global__ __launch_bounds__(256) void spmm_leaky_kernel(float* __restrict__ out)
{
    int gid  = blockIdx.x * 256 + threadIdx.x;
    int row  = gid >> 4;
    if (row >= NN) return;
    int sub  = gid & 15;
    int c0   = sub * 4;

    int s = g_rowptr[row];
    int e = g_rowptr[row + 1];

    float4 a = make_float4(0.f, 0.f, 0.f, 0.f);

    for (int base = s; base < e; base += 16) {
        int   ep = base + sub;
        float2 ev = (ep < e) ? g_edge[ep] : make_float2(__int_as_float(0), 0.f);
        int ci = __float_as_int(ev.x);
        int cnt = min(16, e - base);

        #pragma unroll 4
        for (int j = 0; j < cnt; j++) {
            int   col = __shfl_sync(FULL, ci,   j, 16);
            float v   = __shfl_sync(FULL, ev.y, j, 16);
            float4 x  = *reinterpret_cast<const float4*>(&g_X[col * DOUT + c0]);
            a.x = fmaf(v, x.x, a.x);
            a.y = fmaf(v, x.y, a.y);
            a.z = fmaf(v, x.z, a.z);
            a.w = fmaf(v, x.w, a.w);
        }
    }

    a.x = a.x >= 0.f ? a.x : 0.01f * a.x;
    a.y = a.y >= 0.f ? a.y : 0.01f * a.y;
    a.z = a.z >= 0.f ? a.z : 0.01f * a.z;
    a.w = a.w >= 0.f ? a.w : 0.01f * a.w;

    *reinterpret_cast<float4*>(&out[row * DOUT + c0]) = a;
}

// ---------------------------------------------------------------------------
// Launch: CSR chain (3 kernels) on s0 ∥ GEMM on s1; SpMM joins.
// ---------------------------------------------------------------------------
extern "C" void kernel_launch(void* const* d_in, const int* in_sizes, int n_in,
                              void* d_out, int out_size) {
    const float* H     = (const float*)d_in[0];
    const int*   rows  = (const int*)  d_in[1];
    const int*   cols  = (const int*)  d_in[2];
    const float* vals  = (const float*)d_in[3];
    const float* gamma = (const float*)d_in[4];
    const float* beta  = (const float*)d_in[5];
    const float* rmean = (const float*)d_in[6];
    const float* rvar  = (const float*)d_in[7];
    const float* W     = (const float*)d_in[8];
    const float* b     = (const float*)d_in[9];
    float* out = (float*)d_out;

    cudaStream_t s0 = 0;
    cudaStream_t s1;
    cudaEvent_t  evFork, evJoin;
    cudaStreamCreateWithFlags(&s1, cudaStreamNonBlocking);
    cudaEventCreateWithFlags(&evFork, cudaEventDisableTiming);
    cudaEventCreateWithFlags(&evJoin, cudaEventDisableTiming);

    // Fork: GEMM on s1
    cudaEventRecord(evFork, s0);
    cudaStreamWaitEvent(s1, evFork, 0);
    fused_gemm_kernel<<<(NN + GTILE - 1) / GTILE, 128, 0, s1>>>(
        H, gamma, beta, rmean, rvar, W, b);
    cudaEventRecord(evJoin, s1);

    // CSR build chain on s0 (concurrent with GEMM)
    hist_kernel<<<(EE / 4 + 255) / 256, 256, 0, s0>>>(rows);
    scan_kernel<<<NSB, 256, 0, s0>>>();
    scatter_kernel<<<(EE + 255) / 256, 256, 0, s0>>>(rows, cols, vals);

    // Join: SpMM needs both g_X (s1) and CSR arrays (s0)
    cudaStreamWaitEvent(s0, evJoin, 0);
    spmm_leaky_kernel<<<(NN * 16 + 255) / 256, 256, 0, s0>>>(out);

    cudaEventDestroy(evFork);
    cudaEventDestroy(evJoin);
    cudaStreamDestroy(s1);
}